// round 8
// baseline (speedup 1.0000x reference)
#include <cuda_runtime.h>
#include <cuda_bf16.h>

#define NMAX 100000
#define EMAX 1700000
#define FDIM 128
#define HDIM 64

// ---------------- scratch (static device globals; no runtime alloc) -------
__device__ int   d_is32;                 // 1 if edge buffers are int32
__device__ int   d_deg[NMAX];
__device__ int   d_rowptr[NMAX + 1];     // CSR row offsets (by target node)
__device__ int   d_cur[NMAX];            // fill cursors
__device__ int   d_csr[EMAX];            // CSR column data: source node ids
__device__ float d_dinv[NMAX];
__device__ float d_G   [NMAX * HDIM];    // g1, then g2 (reused)
__device__ float d_ACC [NMAX * HDIM];    // TD = H2 @ Wb^T
__device__ float d_H   [NMAX * HDIM];    // H1, then H2 (reused)
__device__ float d_Wc  [FDIM * HDIM];    // W0 @ W1
__device__ float d_bc  [HDIM];           // b0 @ W1
__device__ float d_WbT [HDIM * HDIM];    // Wb[0]^T
__device__ int   d_EPRED[2 * EMAX];      // normalized int32 prediction edges
__device__ int   d_EPOS [2 * EMAX];      // normalized int32 message edges

// ---------------- zero deg + flag ------------------------------------------
__global__ void __launch_bounds__(256) k_zero(int n) {
    int i = blockIdx.x * blockDim.x + threadIdx.x;
    if (i == 0) d_is32 = 0;
    if (i < n) d_deg[i] = 0;
}

// ---------------- edge dtype detection (sampled) ---------------------------
// Reads odd 32-bit words among the first 4096 words (safe under both dtypes).
// int64 little-endian with ids < 2^31 => every odd word == 0.
// int32 => odd words are node ids; P(all 2048 sampled ids == 0) ~ 0.
__global__ void __launch_bounds__(256) k_detect(const unsigned int* __restrict__ w,
                                                int nwords2) {
    int i = blockIdx.x * blockDim.x + threadIdx.x;   // 2048 threads
    int idx = 2 * i + 1;
    if (idx < nwords2 && idx < 4096 && w[idx] != 0u) d_is32 = 1;
}

// ---------------- normalize pred edges to int32 ----------------------------
__global__ void __launch_bounds__(256) k_norm_pred(const int* __restrict__ buf, int n2) {
    int i = blockIdx.x * blockDim.x + threadIdx.x;
    if (i >= n2) return;
    d_EPRED[i] = d_is32 ? buf[i] : buf[2 * i];   // int64 LE: low word
}

// ---------------- normalize pos edges + count degree (fused) ---------------
__global__ void __launch_bounds__(256) k_norm_pos(const int* __restrict__ buf, int E) {
    int i = blockIdx.x * blockDim.x + threadIdx.x;
    if (i >= 2 * E) return;
    int v = d_is32 ? buf[i] : buf[2 * i];
    d_EPOS[i] = v;
    if (i >= E) atomicAdd(&d_deg[v], 1);         // second half = targets
}

// ---------------- 1-block prefix scan: rowptr, cursors, dinv ---------------
__global__ void __launch_bounds__(1024) k_scan(int n) {
    __shared__ int sh[1024];
    int t = threadIdx.x;
    int chunk = (n + 1023) / 1024;
    int beg = t * chunk, end = min(beg + chunk, n);
    int s = 0;
    for (int i = beg; i < end; i++) s += d_deg[i];
    sh[t] = s;
    __syncthreads();
    // Hillis-Steele inclusive scan
    for (int off = 1; off < 1024; off <<= 1) {
        int v = (t >= off) ? sh[t - off] : 0;
        __syncthreads();
        sh[t] += v;
        __syncthreads();
    }
    int run = (t == 0) ? 0 : sh[t - 1];
    for (int i = beg; i < end; i++) {
        int d = d_deg[i];
        d_rowptr[i] = run;
        d_cur[i]    = run;
        d_dinv[i]   = rsqrtf((float)(d + 1));    // +1 self loop
        run += d;
    }
    if (t == 1023) d_rowptr[n] = sh[1023];
}

// ---------------- CSR fill --------------------------------------------------
__global__ void __launch_bounds__(256) k_fill(int E) {
    int i = blockIdx.x * blockDim.x + threadIdx.x;
    if (i >= E) return;
    int src = d_EPOS[i];
    int dst = d_EPOS[E + i];
    int pos = atomicAdd(&d_cur[dst], 1);
    d_csr[pos] = src;
}

// ---------------- tiny weight prep: Wc = W0@W1, bc = b0@W1, WbT -----------
__global__ void __launch_bounds__(256) k_prep(const float* __restrict__ W0,
                                              const float* __restrict__ b0,
                                              const float* __restrict__ W1,
                                              const float* __restrict__ Wb) {
    int t = blockIdx.x * blockDim.x + threadIdx.x;
    if (t < FDIM * HDIM) {
        int k = t / HDIM, o = t % HDIM;
        float s = 0.f;
        #pragma unroll 8
        for (int m = 0; m < FDIM; m++) s += W0[k * FDIM + m] * W1[m * HDIM + o];
        d_Wc[t] = s;
    }
    if (t < HDIM) {
        float s = 0.f;
        for (int m = 0; m < FDIM; m++) s += b0[m] * W1[m * HDIM + t];
        d_bc[t] = s;
    }
    if (t < HDIM * HDIM) {
        int i = t / HDIM, j = t % HDIM;
        d_WbT[j * HDIM + i] = Wb[t];   // WbT[j][i] = Wb[i][j]
    }
}

// ---------------- tiled fp32 GEMM: C[M,64] = A[M,K] @ B[K,64] -------------
//   AG: 0 = Ain param, 1 = d_H
//   BG: 0 = Bin param, 1 = d_Wc, 2 = d_WbT
//   CG: 1 = d_G, 2 = d_ACC
//   BIASG: 0 = none, 1 = d_bc
//   SCALE: multiply each output row by d_dinv[row]
template <int K, int AG, int BG, int CG, int BIASG, int SCALE>
__global__ void __launch_bounds__(256) gemm64(const float* __restrict__ Ain,
                                              const float* __restrict__ Bin,
                                              int M) {
    const float* A = (AG == 1) ? d_H : Ain;
    const float* B = (BG == 1) ? d_Wc : (BG == 2) ? d_WbT : Bin;
    float*       C = (CG == 1) ? d_G : d_ACC;

    __shared__ float Bs[K][68];
    __shared__ float As[16][68];
    const int tid = threadIdx.x;

    for (int idx = tid; idx < K * 16; idx += 256) {
        int k = idx >> 4, c4 = (idx & 15) << 2;
        float4 v = *(const float4*)(B + k * 64 + c4);
        *(float4*)&Bs[k][c4] = v;
    }

    const int bm = blockIdx.x * 64;
    const int tr = tid >> 4;
    const int tc = tid & 15;
    const int lrow = tid >> 2;
    const int lk   = (tid & 3) << 2;

    float acc[4][4] = {};

    for (int kc = 0; kc < K; kc += 16) {
        float4 av = make_float4(0.f, 0.f, 0.f, 0.f);
        int grow = bm + lrow;
        if (grow < M) av = *(const float4*)(A + (size_t)grow * K + kc + lk);
        __syncthreads();
        As[lk + 0][lrow] = av.x;
        As[lk + 1][lrow] = av.y;
        As[lk + 2][lrow] = av.z;
        As[lk + 3][lrow] = av.w;
        __syncthreads();
        #pragma unroll
        for (int k = 0; k < 16; k++) {
            float4 a = *(const float4*)&As[k][tr * 4];
            float4 b = *(const float4*)&Bs[kc + k][tc * 4];
            acc[0][0] += a.x * b.x; acc[0][1] += a.x * b.y; acc[0][2] += a.x * b.z; acc[0][3] += a.x * b.w;
            acc[1][0] += a.y * b.x; acc[1][1] += a.y * b.y; acc[1][2] += a.y * b.z; acc[1][3] += a.y * b.w;
            acc[2][0] += a.z * b.x; acc[2][1] += a.z * b.y; acc[2][2] += a.z * b.z; acc[2][3] += a.z * b.w;
            acc[3][0] += a.w * b.x; acc[3][1] += a.w * b.y; acc[3][2] += a.w * b.z; acc[3][3] += a.w * b.w;
        }
    }

    #pragma unroll
    for (int i = 0; i < 4; i++) {
        int r = bm + tr * 4 + i;
        if (r >= M) continue;
        float s = SCALE ? d_dinv[r] : 1.f;
        #pragma unroll
        for (int j = 0; j < 4; j++) {
            float v = acc[i][j];
            if (BIASG == 1) v += d_bc[tc * 4 + j];
            C[r * 64 + tc * 4 + j] = v * s;
        }
    }
}

// ---------------- pull aggregation + fused finalize -------------------------
// One warp per node. Half-warps process alternating neighbors (2 in flight).
// H[n] = [relu]( dinv[n] * (sum_{src->n} G[src] + G[n]) + b )
template <int RELU>
__global__ void __launch_bounds__(256) k_pull(const float* __restrict__ b, int N) {
    int warp = (blockIdx.x * blockDim.x + threadIdx.x) >> 5;
    if (warp >= N) return;
    int lane = threadIdx.x & 31;
    int half = lane >> 4;        // 0 or 1
    int c    = lane & 15;        // feature float4 chunk

    int beg = d_rowptr[warp];
    int end = d_rowptr[warp + 1];

    float4 acc = make_float4(0.f, 0.f, 0.f, 0.f);
    for (int j = beg + half; j < end; j += 2) {
        int src = __ldg(&d_csr[j]);
        float4 v = __ldg((const float4*)(d_G + (size_t)src * 64 + c * 4));
        acc.x += v.x; acc.y += v.y; acc.z += v.z; acc.w += v.w;
    }
    // combine the two half-warp partials (same c, different neighbor set)
    acc.x += __shfl_xor_sync(0xffffffffu, acc.x, 16);
    acc.y += __shfl_xor_sync(0xffffffffu, acc.y, 16);
    acc.z += __shfl_xor_sync(0xffffffffu, acc.z, 16);
    acc.w += __shfl_xor_sync(0xffffffffu, acc.w, 16);

    if (half == 0) {
        float4 g  = *(const float4*)(d_G + (size_t)warp * 64 + c * 4);
        float4 bv = *(const float4*)(b + c * 4);
        float s = d_dinv[warp];
        float4 o;
        o.x = s * (acc.x + g.x) + bv.x;
        o.y = s * (acc.y + g.y) + bv.y;
        o.z = s * (acc.z + g.z) + bv.z;
        o.w = s * (acc.w + g.w) + bv.w;
        if (RELU) {
            o.x = fmaxf(o.x, 0.f); o.y = fmaxf(o.y, 0.f);
            o.z = fmaxf(o.z, 0.f); o.w = fmaxf(o.w, 0.f);
        }
        *(float4*)(d_H + (size_t)warp * 64 + c * 4) = o;
    }
}

// ---------------- bilinear decoder: out[e] = H2[src]·TD[dst] + bb ---------
__global__ void __launch_bounds__(256) k_bilinear(int E, const float* __restrict__ bb,
                                                  float* __restrict__ out) {
    int total = E * 16;
    for (int t = blockIdx.x * blockDim.x + threadIdx.x; t < total;
         t += gridDim.x * blockDim.x) {
        int e = t >> 4, c = t & 15;
        int s = __ldg(&d_EPRED[e]);
        int d = __ldg(&d_EPRED[E + e]);
        float4 a = __ldg((const float4*)(d_H   + (size_t)s * 64 + c * 4));
        float4 b = __ldg((const float4*)(d_ACC + (size_t)d * 64 + c * 4)); // TD
        float p = a.x * b.x + a.y * b.y + a.z * b.z + a.w * b.w;
        p += __shfl_xor_sync(0xffffffffu, p, 8);
        p += __shfl_xor_sync(0xffffffffu, p, 4);
        p += __shfl_xor_sync(0xffffffffu, p, 2);
        p += __shfl_xor_sync(0xffffffffu, p, 1);
        if (c == 0) out[e] = p + bb[0];
    }
}

// ---------------- launcher: kernel launches ONLY ---------------------------
extern "C" void kernel_launch(void* const* d_in, const int* in_sizes, int n_in,
                              void* d_out, int out_size) {
    const float* x     = (const float*)d_in[0];
    const int*   eip   = (const int*)d_in[1];    // prediction edges (raw words)
    const int*   eipos = (const int*)d_in[2];    // message edges (raw words)
    const float* W0    = (const float*)d_in[3];
    const float* b0    = (const float*)d_in[4];
    const float* W1    = (const float*)d_in[5];
    const float* b1    = (const float*)d_in[6];
    const float* W2    = (const float*)d_in[7];
    const float* b2    = (const float*)d_in[8];
    const float* Wb    = (const float*)d_in[9];
    const float* bb    = (const float*)d_in[10];
    float* out = (float*)d_out;

    const int N     = in_sizes[0] / FDIM;
    const int Epred = in_sizes[1] / 2;
    const int Epos  = in_sizes[2] / 2;
    const int GS    = 8192;

    // init + dtype detect + normalize (degree fused into pos-normalize)
    k_zero<<<(N + 255) / 256, 256>>>(N);
    k_detect<<<8, 256>>>((const unsigned int*)eip, 2 * Epred);
    k_norm_pred<<<(2 * Epred + 255) / 256, 256>>>(eip, 2 * Epred);
    k_norm_pos<<<(2 * Epos + 255) / 256, 256>>>(eipos, Epos);

    // CSR build: rowptr/cursors/dinv then fill
    k_scan<<<1, 1024>>>(N);
    k_fill<<<(Epos + 255) / 256, 256>>>(Epos);

    // weight prep: Wc = W0@W1, bc = b0@W1, WbT
    k_prep<<<32, 256>>>(W0, b0, W1, Wb);

    // g1 = (x @ Wc + bc) * dinv[row]
    gemm64<FDIM, 0, 1, 1, 1, 1><<<(N + 63) / 64, 256>>>(x, nullptr, N);

    // conv1: pull + fused finalize -> H1 (relu)
    k_pull<1><<<(N * 32 + 255) / 256, 256>>>(b1, N);

    // g2 = (H1 @ W2) * dinv[row]
    gemm64<HDIM, 1, 0, 1, 0, 1><<<(N + 63) / 64, 256>>>(nullptr, W2, N);

    // conv2: pull + fused finalize -> H2 (no relu)
    k_pull<0><<<(N * 32 + 255) / 256, 256>>>(b2, N);

    // TD = H2 @ Wb^T -> d_ACC
    gemm64<HDIM, 1, 2, 2, 0, 0><<<(N + 63) / 64, 256>>>(nullptr, nullptr, N);

    // logits[e] = H2[src] · TD[dst] + bb
    k_bilinear<<<GS, 256>>>(Epred, bb, out);
}

// round 10
// speedup vs baseline: 1.3350x; 1.3350x over previous
#include <cuda_runtime.h>
#include <cuda_bf16.h>

#define NMAX 100000
#define EMAX 1700000
#define FDIM 128
#define HDIM 64

// ---------------- scratch (static device globals; no runtime alloc) -------
__device__ int   d_is32;                 // 1 if edge buffers are int32
__device__ int   d_deg[NMAX];
__device__ float d_dinv[NMAX];
__device__ float d_G   [NMAX * HDIM];    // g1, then g2
__device__ float d_ACC [NMAX * HDIM];    // acc1 (seeded with g1), then TD
__device__ float d_ACC2[NMAX * HDIM];    // acc2 (seeded with g2)
__device__ float d_H   [NMAX * HDIM];    // H2 (written by gemm3 A-loader)
__device__ float d_Wc  [FDIM * HDIM];    // W0 @ W1
__device__ float d_bc  [HDIM];           // b0 @ W1
__device__ float d_WbT [HDIM * HDIM];    // Wb[0]^T
__device__ int   d_EPRED[2 * EMAX];      // normalized int32 prediction edges
__device__ int   d_EPOS [2 * EMAX];      // normalized int32 message edges

// ---------------- vector reduction helper ----------------------------------
__device__ __forceinline__ void red_add_v4(float* p, float4 v) {
#if __CUDA_ARCH__ >= 900
    asm volatile("red.global.add.v4.f32 [%0], {%1, %2, %3, %4};"
                 :: "l"(p), "f"(v.x), "f"(v.y), "f"(v.z), "f"(v.w)
                 : "memory");
#else
    atomicAdd(p + 0, v.x); atomicAdd(p + 1, v.y);
    atomicAdd(p + 2, v.z); atomicAdd(p + 3, v.w);
#endif
}

// ---------------- zero deg + flag ------------------------------------------
__global__ void __launch_bounds__(256) k_zero(int n) {
    int i = blockIdx.x * blockDim.x + threadIdx.x;
    if (i == 0) d_is32 = 0;
    if (i < n) d_deg[i] = 0;
}

// ---------------- edge dtype detection (sampled) ---------------------------
// int64 LE with ids < 2^31 => every odd 32-bit word == 0.
// int32 => odd words are node ids; P(2048 sampled ids all zero) ~ 0.
__global__ void __launch_bounds__(256) k_detect(const unsigned int* __restrict__ w,
                                                int nwords2) {
    int i = blockIdx.x * blockDim.x + threadIdx.x;   // 2048 threads
    int idx = 2 * i + 1;
    if (idx < nwords2 && idx < 4096 && w[idx] != 0u) d_is32 = 1;
}

// ---------------- normalize pred edges to int32 ----------------------------
__global__ void __launch_bounds__(256) k_norm_pred(const int* __restrict__ buf, int n2) {
    int i = blockIdx.x * blockDim.x + threadIdx.x;
    if (i >= n2) return;
    d_EPRED[i] = d_is32 ? buf[i] : buf[2 * i];   // int64 LE: low word
}

// ---------------- normalize pos edges + count degree (fused) ---------------
__global__ void __launch_bounds__(256) k_norm_pos(const int* __restrict__ buf, int E) {
    int i = blockIdx.x * blockDim.x + threadIdx.x;
    if (i >= 2 * E) return;
    int v = d_is32 ? buf[i] : buf[2 * i];
    d_EPOS[i] = v;
    if (i >= E) atomicAdd(&d_deg[v], 1);         // second half = targets
}

__global__ void __launch_bounds__(256) k_dinv(int n) {
    int i = blockIdx.x * blockDim.x + threadIdx.x;
    if (i < n) d_dinv[i] = rsqrtf((float)(d_deg[i] + 1));  // +1 self loop
}

// ---------------- tiny weight prep: Wc = W0@W1, bc = b0@W1, WbT -----------
__global__ void __launch_bounds__(256) k_prep(const float* __restrict__ W0,
                                              const float* __restrict__ b0,
                                              const float* __restrict__ W1,
                                              const float* __restrict__ Wb) {
    int t = blockIdx.x * blockDim.x + threadIdx.x;
    if (t < FDIM * HDIM) {
        int k = t / HDIM, o = t % HDIM;
        float s = 0.f;
        #pragma unroll 8
        for (int m = 0; m < FDIM; m++) s += W0[k * FDIM + m] * W1[m * HDIM + o];
        d_Wc[t] = s;
    }
    if (t < HDIM) {
        float s = 0.f;
        for (int m = 0; m < FDIM; m++) s += b0[m] * W1[m * HDIM + t];
        d_bc[t] = s;
    }
    if (t < HDIM * HDIM) {
        int i = t / HDIM, j = t % HDIM;
        d_WbT[j * HDIM + i] = Wb[t];   // WbT[j][i] = Wb[i][j]
    }
}

// ---------------- fused GEMM: C[M,64] = f(A)[M,K] @ B[K,64] ---------------
// MODE 0: A = Ain (x), B = d_Wc.   C = (A@B + bc)*dinv -> d_G AND d_ACC (seed)
// MODE 1: A = relu(dinv*acc1 + b1) (finalize conv1 in loader), B = Bin (W2).
//         C = (A@B)*dinv -> d_G AND d_ACC2 (seed)
// MODE 2: A = dinv*acc2 + b2 = H2 (finalize conv2 in loader; side-store d_H),
//         B = d_WbT. C = A@B -> d_ACC (TD; acc1 dead)
template <int K, int MODE>
__global__ void __launch_bounds__(256) gemmF(const float* __restrict__ Ain,
                                             const float* __restrict__ Bin,
                                             const float* __restrict__ bA,
                                             int M) {
    const float* B = (MODE == 0) ? d_Wc : (MODE == 2) ? d_WbT : Bin;

    __shared__ float Bs[K][68];
    __shared__ float As[16][68];
    const int tid = threadIdx.x;

    for (int idx = tid; idx < K * 16; idx += 256) {
        int k = idx >> 4, c4 = (idx & 15) << 2;
        float4 v = *(const float4*)(B + k * 64 + c4);
        *(float4*)&Bs[k][c4] = v;
    }

    const int bm = blockIdx.x * 64;
    const int tr = tid >> 4;
    const int tc = tid & 15;
    const int lrow = tid >> 2;
    const int lk   = (tid & 3) << 2;

    float acc[4][4] = {};

    for (int kc = 0; kc < K; kc += 16) {
        float4 av = make_float4(0.f, 0.f, 0.f, 0.f);
        int grow = bm + lrow;
        if (grow < M) {
            if (MODE == 0) {
                av = *(const float4*)(Ain + (size_t)grow * K + kc + lk);
            } else {
                const float* accsrc = (MODE == 1) ? d_ACC : d_ACC2;
                float4 a4 = *(const float4*)(accsrc + (size_t)grow * 64 + kc + lk);
                float4 bv = *(const float4*)(bA + kc + lk);
                float s = d_dinv[grow];
                av.x = s * a4.x + bv.x;
                av.y = s * a4.y + bv.y;
                av.z = s * a4.z + bv.z;
                av.w = s * a4.w + bv.w;
                if (MODE == 1) {
                    av.x = fmaxf(av.x, 0.f); av.y = fmaxf(av.y, 0.f);
                    av.z = fmaxf(av.z, 0.f); av.w = fmaxf(av.w, 0.f);
                }
                if (MODE == 2)   // side-effect: store H2 (each element once)
                    *(float4*)(d_H + (size_t)grow * 64 + kc + lk) = av;
            }
        }
        __syncthreads();                 // prev chunk consumed
        As[lk + 0][lrow] = av.x;
        As[lk + 1][lrow] = av.y;
        As[lk + 2][lrow] = av.z;
        As[lk + 3][lrow] = av.w;
        __syncthreads();
        #pragma unroll
        for (int k = 0; k < 16; k++) {
            float4 a = *(const float4*)&As[k][tr * 4];
            float4 b = *(const float4*)&Bs[kc + k][tc * 4];
            acc[0][0] += a.x * b.x; acc[0][1] += a.x * b.y; acc[0][2] += a.x * b.z; acc[0][3] += a.x * b.w;
            acc[1][0] += a.y * b.x; acc[1][1] += a.y * b.y; acc[1][2] += a.y * b.z; acc[1][3] += a.y * b.w;
            acc[2][0] += a.z * b.x; acc[2][1] += a.z * b.y; acc[2][2] += a.z * b.z; acc[2][3] += a.z * b.w;
            acc[3][0] += a.w * b.x; acc[3][1] += a.w * b.y; acc[3][2] += a.w * b.z; acc[3][3] += a.w * b.w;
        }
    }

    #pragma unroll
    for (int i = 0; i < 4; i++) {
        int r = bm + tr * 4 + i;
        if (r >= M) continue;
        float s = (MODE == 2) ? 1.f : d_dinv[r];
        #pragma unroll
        for (int j = 0; j < 4; j++) {
            float v = acc[i][j];
            if (MODE == 0) v += d_bc[tc * 4 + j];
            v *= s;
            size_t o = (size_t)r * 64 + tc * 4 + j;
            if (MODE == 0) { d_G[o] = v; d_ACC[o]  = v; }   // seed acc1 = g1
            if (MODE == 1) { d_G[o] = v; d_ACC2[o] = v; }   // seed acc2 = g2
            if (MODE == 2) { d_ACC[o] = v; }                // TD
        }
    }
}

// ---------------- edge scatter-add: acc[col] += g[row] --------------------
// 16 threads per edge, float4 gather, ONE red.global.add.v4.f32 each.
template <int WHICH>   // 1 -> d_ACC, 2 -> d_ACC2
__global__ void __launch_bounds__(256) k_scatter(int E) {
    int total = E * 16;
    for (int t = blockIdx.x * blockDim.x + threadIdx.x; t < total;
         t += gridDim.x * blockDim.x) {
        int e = t >> 4, c = t & 15;
        int r  = __ldg(&d_EPOS[e]);
        int cl = __ldg(&d_EPOS[E + e]);
        float4 v = __ldg((const float4*)(d_G + (size_t)r * 64 + c * 4));
        float* p = (WHICH == 1 ? d_ACC : d_ACC2) + (size_t)cl * 64 + c * 4;
        red_add_v4(p, v);
    }
}

// ---------------- bilinear decoder: out[e] = H2[src]·TD[dst] + bb ---------
__global__ void __launch_bounds__(256) k_bilinear(int E, const float* __restrict__ bb,
                                                  float* __restrict__ out) {
    int total = E * 16;
    for (int t = blockIdx.x * blockDim.x + threadIdx.x; t < total;
         t += gridDim.x * blockDim.x) {
        int e = t >> 4, c = t & 15;
        int s = __ldg(&d_EPRED[e]);
        int d = __ldg(&d_EPRED[E + e]);
        float4 a = __ldg((const float4*)(d_H   + (size_t)s * 64 + c * 4));
        float4 b = __ldg((const float4*)(d_ACC + (size_t)d * 64 + c * 4)); // TD
        float p = a.x * b.x + a.y * b.y + a.z * b.z + a.w * b.w;
        p += __shfl_xor_sync(0xffffffffu, p, 8);
        p += __shfl_xor_sync(0xffffffffu, p, 4);
        p += __shfl_xor_sync(0xffffffffu, p, 2);
        p += __shfl_xor_sync(0xffffffffu, p, 1);
        if (c == 0) out[e] = p + bb[0];
    }
}

// ---------------- launcher: kernel launches ONLY ---------------------------
extern "C" void kernel_launch(void* const* d_in, const int* in_sizes, int n_in,
                              void* d_out, int out_size) {
    const float* x     = (const float*)d_in[0];
    const int*   eip   = (const int*)d_in[1];    // prediction edges (raw words)
    const int*   eipos = (const int*)d_in[2];    // message edges (raw words)
    const float* W0    = (const float*)d_in[3];
    const float* b0    = (const float*)d_in[4];
    const float* W1    = (const float*)d_in[5];
    const float* b1    = (const float*)d_in[6];
    const float* W2    = (const float*)d_in[7];
    const float* b2    = (const float*)d_in[8];
    const float* Wb    = (const float*)d_in[9];
    const float* bb    = (const float*)d_in[10];
    float* out = (float*)d_out;

    const int N     = in_sizes[0] / FDIM;
    const int Epred = in_sizes[1] / 2;
    const int Epos  = in_sizes[2] / 2;
    const int GS    = 8192;

    // init + dtype detect + normalize (degree fused into pos-normalize)
    k_zero<<<(N + 255) / 256, 256>>>(N);
    k_detect<<<8, 256>>>((const unsigned int*)eip, 2 * Epred);
    k_norm_pred<<<(2 * Epred + 255) / 256, 256>>>(eip, 2 * Epred);
    k_norm_pos<<<(2 * Epos + 255) / 256, 256>>>(eipos, Epos);
    k_dinv<<<(N + 255) / 256, 256>>>(N);

    // weight prep: Wc = W0@W1, bc = b0@W1, WbT
    k_prep<<<32, 256>>>(W0, b0, W1, Wb);

    // g1 = (x@Wc + bc)*dinv  -> d_G, and seeds acc1 (self-loop term)
    gemmF<FDIM, 0><<<(N + 63) / 64, 256>>>(x, nullptr, nullptr, N);

    // conv1 aggregate: acc1[col] += g1[row]
    k_scatter<1><<<GS, 256>>>(Epos);

    // g2 = (relu(dinv*acc1 + b1) @ W2)*dinv -> d_G, seeds acc2
    gemmF<HDIM, 1><<<(N + 63) / 64, 256>>>(nullptr, W2, b1, N);

    // conv2 aggregate: acc2[col] += g2[row]
    k_scatter<2><<<GS, 256>>>(Epos);

    // H2 = dinv*acc2 + b2 (stored to d_H in loader); TD = H2@WbT -> d_ACC
    gemmF<HDIM, 2><<<(N + 63) / 64, 256>>>(nullptr, nullptr, b2, N);

    // logits[e] = H2[src] · TD[dst] + bb
    k_bilinear<<<GS, 256>>>(Epred, bb, out);
}

// round 11
// speedup vs baseline: 1.5739x; 1.1789x over previous
#include <cuda_runtime.h>
#include <cuda_fp16.h>

#define NMAX 100000
#define EMAX 1700000
#define FDIM 128
#define HDIM 64

// ---------------- scratch (static device globals; no runtime alloc) -------
__device__ int    d_is32;                // 1 if edge buffers are int32
__device__ int    d_deg[NMAX];
__device__ float  d_dinv[NMAX];
__device__ float  d_G   [NMAX * HDIM];   // g1, then g2
__device__ float  d_ACC [NMAX * HDIM];   // acc1 (seeded with g1)
__device__ float  d_ACC2[NMAX * HDIM];   // acc2 (seeded with g2)
__device__ __half d_Hh  [NMAX * HDIM];   // H2 in fp16 (gemm3 A-loader side-store)
__device__ __half d_TDh [NMAX * HDIM];   // TD = H2 @ Wb^T in fp16
__device__ float  d_Wc  [FDIM * HDIM];   // W0 @ W1
__device__ float  d_bc  [HDIM];          // b0 @ W1
__device__ float  d_WbT [HDIM * HDIM];   // Wb[0]^T
__device__ int    d_EPOS[2 * EMAX];      // normalized int32 message edges

// ---------------- vector reduction helper ----------------------------------
__device__ __forceinline__ void red_add_v4(float* p, float4 v) {
#if __CUDA_ARCH__ >= 900
    asm volatile("red.global.add.v4.f32 [%0], {%1, %2, %3, %4};"
                 :: "l"(p), "f"(v.x), "f"(v.y), "f"(v.z), "f"(v.w)
                 : "memory");
#else
    atomicAdd(p + 0, v.x); atomicAdd(p + 1, v.y);
    atomicAdd(p + 2, v.z); atomicAdd(p + 3, v.w);
#endif
}

// ---------------- zero deg + flag ------------------------------------------
__global__ void __launch_bounds__(256) k_zero(int n) {
    int i = blockIdx.x * blockDim.x + threadIdx.x;
    if (i == 0) d_is32 = 0;
    if (i < n) d_deg[i] = 0;
}

// ---------------- edge dtype detection (sampled) ---------------------------
// int64 LE with ids < 2^31 => every odd 32-bit word == 0.
// int32 => odd words are node ids; P(2048 sampled ids all zero) ~ 0.
__global__ void __launch_bounds__(256) k_detect(const unsigned int* __restrict__ w,
                                                int nwords2) {
    int i = blockIdx.x * blockDim.x + threadIdx.x;   // 2048 threads
    int idx = 2 * i + 1;
    if (idx < nwords2 && idx < 4096 && w[idx] != 0u) d_is32 = 1;
}

// ---------------- normalize pos edges + count degree (fused) ---------------
__global__ void __launch_bounds__(256) k_norm_pos(const int* __restrict__ buf, int E) {
    int i = blockIdx.x * blockDim.x + threadIdx.x;
    if (i >= 2 * E) return;
    int v = d_is32 ? buf[i] : buf[2 * i];
    d_EPOS[i] = v;
    if (i >= E) atomicAdd(&d_deg[v], 1);         // second half = targets
}

__global__ void __launch_bounds__(256) k_dinv(int n) {
    int i = blockIdx.x * blockDim.x + threadIdx.x;
    if (i < n) d_dinv[i] = rsqrtf((float)(d_deg[i] + 1));  // +1 self loop
}

// ---------------- tiny weight prep: Wc = W0@W1, bc = b0@W1, WbT -----------
__global__ void __launch_bounds__(256) k_prep(const float* __restrict__ W0,
                                              const float* __restrict__ b0,
                                              const float* __restrict__ W1,
                                              const float* __restrict__ Wb) {
    int t = blockIdx.x * blockDim.x + threadIdx.x;
    if (t < FDIM * HDIM) {
        int k = t / HDIM, o = t % HDIM;
        float s = 0.f;
        #pragma unroll 8
        for (int m = 0; m < FDIM; m++) s += W0[k * FDIM + m] * W1[m * HDIM + o];
        d_Wc[t] = s;
    }
    if (t < HDIM) {
        float s = 0.f;
        for (int m = 0; m < FDIM; m++) s += b0[m] * W1[m * HDIM + t];
        d_bc[t] = s;
    }
    if (t < HDIM * HDIM) {
        int i = t / HDIM, j = t % HDIM;
        d_WbT[j * HDIM + i] = Wb[t];   // WbT[j][i] = Wb[i][j]
    }
}

// ---------------- fused GEMM: C[M,64] = f(A)[M,K] @ B[K,64] ---------------
// MODE 0: A = Ain (x), B = d_Wc.   C = (A@B + bc)*dinv -> d_G AND d_ACC (seed)
// MODE 1: A = relu(dinv*acc1 + b1) (finalize conv1 in loader), B = Bin (W2).
//         C = (A@B)*dinv -> d_G AND d_ACC2 (seed)
// MODE 2: A = dinv*acc2 + b2 = H2 (finalize conv2 in loader; side-store fp16
//         to d_Hh), B = d_WbT. C = A@B -> d_TDh (fp16)
template <int K, int MODE>
__global__ void __launch_bounds__(256) gemmF(const float* __restrict__ Ain,
                                             const float* __restrict__ Bin,
                                             const float* __restrict__ bA,
                                             int M) {
    const float* B = (MODE == 0) ? d_Wc : (MODE == 2) ? d_WbT : Bin;

    __shared__ float Bs[K][68];
    __shared__ float As[16][68];
    const int tid = threadIdx.x;

    for (int idx = tid; idx < K * 16; idx += 256) {
        int k = idx >> 4, c4 = (idx & 15) << 2;
        float4 v = *(const float4*)(B + k * 64 + c4);
        *(float4*)&Bs[k][c4] = v;
    }

    const int bm = blockIdx.x * 64;
    const int tr = tid >> 4;
    const int tc = tid & 15;
    const int lrow = tid >> 2;
    const int lk   = (tid & 3) << 2;

    float acc[4][4] = {};

    for (int kc = 0; kc < K; kc += 16) {
        float4 av = make_float4(0.f, 0.f, 0.f, 0.f);
        int grow = bm + lrow;
        if (grow < M) {
            if (MODE == 0) {
                av = *(const float4*)(Ain + (size_t)grow * K + kc + lk);
            } else {
                const float* accsrc = (MODE == 1) ? d_ACC : d_ACC2;
                float4 a4 = *(const float4*)(accsrc + (size_t)grow * 64 + kc + lk);
                float4 bv = *(const float4*)(bA + kc + lk);
                float s = d_dinv[grow];
                av.x = s * a4.x + bv.x;
                av.y = s * a4.y + bv.y;
                av.z = s * a4.z + bv.z;
                av.w = s * a4.w + bv.w;
                if (MODE == 1) {
                    av.x = fmaxf(av.x, 0.f); av.y = fmaxf(av.y, 0.f);
                    av.z = fmaxf(av.z, 0.f); av.w = fmaxf(av.w, 0.f);
                }
                if (MODE == 2) {   // side-effect: store H2 fp16 (once per elem)
                    __half2 h01 = __floats2half2_rn(av.x, av.y);
                    __half2 h23 = __floats2half2_rn(av.z, av.w);
                    uint2 pk = make_uint2(*(unsigned*)&h01, *(unsigned*)&h23);
                    *(uint2*)(d_Hh + (size_t)grow * 64 + kc + lk) = pk;
                }
            }
        }
        __syncthreads();                 // prev chunk consumed
        As[lk + 0][lrow] = av.x;
        As[lk + 1][lrow] = av.y;
        As[lk + 2][lrow] = av.z;
        As[lk + 3][lrow] = av.w;
        __syncthreads();
        #pragma unroll
        for (int k = 0; k < 16; k++) {
            float4 a = *(const float4*)&As[k][tr * 4];
            float4 b = *(const float4*)&Bs[kc + k][tc * 4];
            acc[0][0] += a.x * b.x; acc[0][1] += a.x * b.y; acc[0][2] += a.x * b.z; acc[0][3] += a.x * b.w;
            acc[1][0] += a.y * b.x; acc[1][1] += a.y * b.y; acc[1][2] += a.y * b.z; acc[1][3] += a.y * b.w;
            acc[2][0] += a.z * b.x; acc[2][1] += a.z * b.y; acc[2][2] += a.z * b.z; acc[2][3] += a.z * b.w;
            acc[3][0] += a.w * b.x; acc[3][1] += a.w * b.y; acc[3][2] += a.w * b.z; acc[3][3] += a.w * b.w;
        }
    }

    #pragma unroll
    for (int i = 0; i < 4; i++) {
        int r = bm + tr * 4 + i;
        if (r >= M) continue;
        float s = (MODE == 2) ? 1.f : d_dinv[r];
        #pragma unroll
        for (int j = 0; j < 4; j++) {
            float v = acc[i][j];
            if (MODE == 0) v += d_bc[tc * 4 + j];
            acc[i][j] = v * s;
        }
        size_t o = (size_t)r * 64 + tc * 4;
        if (MODE == 0) {
            *(float4*)(d_G + o)   = *(float4*)acc[i];
            *(float4*)(d_ACC + o) = *(float4*)acc[i];    // seed acc1 = g1
        }
        if (MODE == 1) {
            *(float4*)(d_G + o)    = *(float4*)acc[i];
            *(float4*)(d_ACC2 + o) = *(float4*)acc[i];   // seed acc2 = g2
        }
        if (MODE == 2) {                                 // TD in fp16
            __half2 h01 = __floats2half2_rn(acc[i][0], acc[i][1]);
            __half2 h23 = __floats2half2_rn(acc[i][2], acc[i][3]);
            uint2 pk = make_uint2(*(unsigned*)&h01, *(unsigned*)&h23);
            *(uint2*)(d_TDh + o) = pk;
        }
    }
}

// ---------------- edge scatter-add: acc[col] += g[row] --------------------
// 16 threads per edge, float4 gather, ONE red.global.add.v4.f32 each.
template <int WHICH>   // 1 -> d_ACC, 2 -> d_ACC2
__global__ void __launch_bounds__(256) k_scatter(int E) {
    int total = E * 16;
    for (int t = blockIdx.x * blockDim.x + threadIdx.x; t < total;
         t += gridDim.x * blockDim.x) {
        int e = t >> 4, c = t & 15;
        int r  = __ldg(&d_EPOS[e]);
        int cl = __ldg(&d_EPOS[E + e]);
        float4 v = __ldg((const float4*)(d_G + (size_t)r * 64 + c * 4));
        float* p = (WHICH == 1 ? d_ACC : d_ACC2) + (size_t)cl * 64 + c * 4;
        red_add_v4(p, v);
    }
}

// ---------------- bilinear decoder: out[e] = H2[src]·TD[dst] + bb ---------
// fp16 tables, 8 threads/edge, 16B loads; raw edge buffer read inline.
__global__ void __launch_bounds__(256) k_bilinear(const int* __restrict__ buf, int E,
                                                  const float* __restrict__ bb,
                                                  float* __restrict__ out) {
    const int is32 = d_is32;
    const float bias = bb[0];
    const uint4* Hp = (const uint4*)d_Hh;    // 8 halves per uint4
    const uint4* Tp = (const uint4*)d_TDh;
    int total = E * 8;
    for (int t = blockIdx.x * blockDim.x + threadIdx.x; t < total;
         t += gridDim.x * blockDim.x) {
        int e = t >> 3, c = t & 7;
        int s = __ldg(&buf[is32 ? e : 2 * e]);
        int d = __ldg(&buf[is32 ? (E + e) : 2 * (E + e)]);
        uint4 a = __ldg(Hp + (size_t)s * 8 + c);
        uint4 b = __ldg(Tp + (size_t)d * 8 + c);
        float p = 0.f;
        {
            float2 fa, fb;
            fa = __half22float2(*(__half2*)&a.x); fb = __half22float2(*(__half2*)&b.x);
            p += fa.x * fb.x + fa.y * fb.y;
            fa = __half22float2(*(__half2*)&a.y); fb = __half22float2(*(__half2*)&b.y);
            p += fa.x * fb.x + fa.y * fb.y;
            fa = __half22float2(*(__half2*)&a.z); fb = __half22float2(*(__half2*)&b.z);
            p += fa.x * fb.x + fa.y * fb.y;
            fa = __half22float2(*(__half2*)&a.w); fb = __half22float2(*(__half2*)&b.w);
            p += fa.x * fb.x + fa.y * fb.y;
        }
        p += __shfl_xor_sync(0xffffffffu, p, 4);
        p += __shfl_xor_sync(0xffffffffu, p, 2);
        p += __shfl_xor_sync(0xffffffffu, p, 1);
        if (c == 0) out[e] = p + bias;
    }
}

// ---------------- launcher: kernel launches ONLY ---------------------------
extern "C" void kernel_launch(void* const* d_in, const int* in_sizes, int n_in,
                              void* d_out, int out_size) {
    const float* x     = (const float*)d_in[0];
    const int*   eip   = (const int*)d_in[1];    // prediction edges (raw words)
    const int*   eipos = (const int*)d_in[2];    // message edges (raw words)
    const float* W0    = (const float*)d_in[3];
    const float* b0    = (const float*)d_in[4];
    const float* W1    = (const float*)d_in[5];
    const float* b1    = (const float*)d_in[6];
    const float* W2    = (const float*)d_in[7];
    const float* b2    = (const float*)d_in[8];
    const float* Wb    = (const float*)d_in[9];
    const float* bb    = (const float*)d_in[10];
    float* out = (float*)d_out;

    const int N     = in_sizes[0] / FDIM;
    const int Epred = in_sizes[1] / 2;
    const int Epos  = in_sizes[2] / 2;
    const int GS    = 8192;

    // init + dtype detect + normalize pos edges (degree fused)
    k_zero<<<(N + 255) / 256, 256>>>(N);
    k_detect<<<8, 256>>>((const unsigned int*)eip, 2 * Epred);
    k_norm_pos<<<(2 * Epos + 255) / 256, 256>>>(eipos, Epos);
    k_dinv<<<(N + 255) / 256, 256>>>(N);

    // weight prep: Wc = W0@W1, bc = b0@W1, WbT
    k_prep<<<32, 256>>>(W0, b0, W1, Wb);

    // g1 = (x@Wc + bc)*dinv  -> d_G, seeds acc1 (self-loop term)
    gemmF<FDIM, 0><<<(N + 63) / 64, 256>>>(x, nullptr, nullptr, N);

    // conv1 aggregate: acc1[col] += g1[row]
    k_scatter<1><<<GS, 256>>>(Epos);

    // g2 = (relu(dinv*acc1 + b1) @ W2)*dinv -> d_G, seeds acc2
    gemmF<HDIM, 1><<<(N + 63) / 64, 256>>>(nullptr, W2, b1, N);

    // conv2 aggregate: acc2[col] += g2[row]
    k_scatter<2><<<GS, 256>>>(Epos);

    // H2 = dinv*acc2 + b2 (fp16 to d_Hh in loader); TD = H2@WbT -> d_TDh fp16
    gemmF<HDIM, 2><<<(N + 63) / 64, 256>>>(nullptr, nullptr, b2, N);

    // logits[e] = H2[src] · TD[dst] + bb   (fp16 tables, raw edge buffer)
    k_bilinear<<<GS, 256>>>(eip, Epred, bb, out);
}

// round 12
// speedup vs baseline: 1.6567x; 1.0526x over previous
#include <cuda_runtime.h>
#include <cuda_fp16.h>

#define NMAX 100000
#define EMAX 1700000
#define FDIM 128
#define HDIM 64

// ---------------- scratch (static device globals; no runtime alloc) -------
__device__ int    d_is32;                // 1 if edge buffers are int32
__device__ int    d_deg[NMAX];
__device__ float  d_dinv[NMAX];
__device__ __half d_Gh  [NMAX * HDIM];   // g1, then g2 (fp16 messages)
__device__ float  d_ACC [NMAX * HDIM];   // acc1 (seeded with g1), f32
__device__ float  d_ACC2[NMAX * HDIM];   // acc2 (seeded with g2), f32
__device__ __half d_Hh  [NMAX * HDIM];   // H2 in fp16 (gemm3 A-loader side-store)
__device__ __half d_TDh [NMAX * HDIM];   // TD = H2 @ Wb^T in fp16
__device__ float  d_Wc  [FDIM * HDIM];   // W0 @ W1
__device__ float  d_bc  [HDIM];          // b0 @ W1
__device__ float  d_WbT [HDIM * HDIM];   // Wb[0]^T

// ---------------- vector reduction helper ----------------------------------
__device__ __forceinline__ void red_add_v4(float* p, float4 v) {
#if __CUDA_ARCH__ >= 900
    asm volatile("red.global.add.v4.f32 [%0], {%1, %2, %3, %4};"
                 :: "l"(p), "f"(v.x), "f"(v.y), "f"(v.z), "f"(v.w)
                 : "memory");
#else
    atomicAdd(p + 0, v.x); atomicAdd(p + 1, v.y);
    atomicAdd(p + 2, v.z); atomicAdd(p + 3, v.w);
#endif
}

// ---------------- init: zero deg + dtype detect (fused) ---------------------
// int64 LE with ids < 2^31 => every odd 32-bit word == 0.
// int32 => odd words are node ids; P(2048 sampled ids all zero) ~ 0.
// (R1/R2 evidence: reading these buffers as int64 produced wild pointers =>
//  buffers are int32 in practice; branch kept for safety.)
__global__ void __launch_bounds__(256) k_init(const unsigned int* __restrict__ w,
                                              int nwords2, int n) {
    int i = blockIdx.x * blockDim.x + threadIdx.x;
    if (i == 0) d_is32 = 0;
    if (i < n) d_deg[i] = 0;
    int idx = 2 * i + 1;
    if (i < 2048 && idx < nwords2 && w[idx] != 0u) d_is32 = 1;
}

// ---------------- degree count (raw edge buffer, targets only) --------------
__global__ void __launch_bounds__(256) k_deg(const int* __restrict__ buf, int E) {
    int i = blockIdx.x * blockDim.x + threadIdx.x;
    if (i >= E) return;
    int v = d_is32 ? buf[E + i] : buf[2 * (E + i)];
    atomicAdd(&d_deg[v], 1);
}

__global__ void __launch_bounds__(256) k_dinv(int n) {
    int i = blockIdx.x * blockDim.x + threadIdx.x;
    if (i < n) d_dinv[i] = rsqrtf((float)(d_deg[i] + 1));  // +1 self loop
}

// ---------------- tiny weight prep: Wc = W0@W1, bc = b0@W1, WbT -----------
__global__ void __launch_bounds__(256) k_prep(const float* __restrict__ W0,
                                              const float* __restrict__ b0,
                                              const float* __restrict__ W1,
                                              const float* __restrict__ Wb) {
    int t = blockIdx.x * blockDim.x + threadIdx.x;
    if (t < FDIM * HDIM) {
        int k = t / HDIM, o = t % HDIM;
        float s = 0.f;
        #pragma unroll 8
        for (int m = 0; m < FDIM; m++) s += W0[k * FDIM + m] * W1[m * HDIM + o];
        d_Wc[t] = s;
    }
    if (t < HDIM) {
        float s = 0.f;
        for (int m = 0; m < FDIM; m++) s += b0[m] * W1[m * HDIM + t];
        d_bc[t] = s;
    }
    if (t < HDIM * HDIM) {
        int i = t / HDIM, j = t % HDIM;
        d_WbT[j * HDIM + i] = Wb[t];   // WbT[j][i] = Wb[i][j]
    }
}

// ---------------- fused GEMM: C[M,64] = f(A)[M,K] @ B[K,64] ---------------
// MODE 0: A = Ain (x), B = d_Wc.  C = (A@B + bc)*dinv -> d_Gh (fp16) + d_ACC seed
// MODE 1: A = relu(dinv*acc1 + b1) (finalize conv1 in loader), B = Bin (W2).
//         C = (A@B)*dinv -> d_Gh (fp16) + d_ACC2 seed
// MODE 2: A = dinv*acc2 + b2 = H2 (finalize conv2 in loader; side-store fp16
//         to d_Hh), B = d_WbT. C = A@B -> d_TDh (fp16)
template <int K, int MODE>
__global__ void __launch_bounds__(256) gemmF(const float* __restrict__ Ain,
                                             const float* __restrict__ Bin,
                                             const float* __restrict__ bA,
                                             int M) {
    const float* B = (MODE == 0) ? d_Wc : (MODE == 2) ? d_WbT : Bin;

    __shared__ float Bs[K][68];
    __shared__ float As[16][68];
    const int tid = threadIdx.x;

    for (int idx = tid; idx < K * 16; idx += 256) {
        int k = idx >> 4, c4 = (idx & 15) << 2;
        float4 v = *(const float4*)(B + k * 64 + c4);
        *(float4*)&Bs[k][c4] = v;
    }

    const int bm = blockIdx.x * 64;
    const int tr = tid >> 4;
    const int tc = tid & 15;
    const int lrow = tid >> 2;
    const int lk   = (tid & 3) << 2;

    float acc[4][4] = {};

    for (int kc = 0; kc < K; kc += 16) {
        float4 av = make_float4(0.f, 0.f, 0.f, 0.f);
        int grow = bm + lrow;
        if (grow < M) {
            if (MODE == 0) {
                av = *(const float4*)(Ain + (size_t)grow * K + kc + lk);
            } else {
                const float* accsrc = (MODE == 1) ? d_ACC : d_ACC2;
                float4 a4 = *(const float4*)(accsrc + (size_t)grow * 64 + kc + lk);
                float4 bv = *(const float4*)(bA + kc + lk);
                float s = d_dinv[grow];
                av.x = s * a4.x + bv.x;
                av.y = s * a4.y + bv.y;
                av.z = s * a4.z + bv.z;
                av.w = s * a4.w + bv.w;
                if (MODE == 1) {
                    av.x = fmaxf(av.x, 0.f); av.y = fmaxf(av.y, 0.f);
                    av.z = fmaxf(av.z, 0.f); av.w = fmaxf(av.w, 0.f);
                }
                if (MODE == 2) {   // side-effect: store H2 fp16 (once per elem)
                    __half2 h01 = __floats2half2_rn(av.x, av.y);
                    __half2 h23 = __floats2half2_rn(av.z, av.w);
                    uint2 pk = make_uint2(*(unsigned*)&h01, *(unsigned*)&h23);
                    *(uint2*)(d_Hh + (size_t)grow * 64 + kc + lk) = pk;
                }
            }
        }
        __syncthreads();                 // prev chunk consumed
        As[lk + 0][lrow] = av.x;
        As[lk + 1][lrow] = av.y;
        As[lk + 2][lrow] = av.z;
        As[lk + 3][lrow] = av.w;
        __syncthreads();
        #pragma unroll
        for (int k = 0; k < 16; k++) {
            float4 a = *(const float4*)&As[k][tr * 4];
            float4 b = *(const float4*)&Bs[kc + k][tc * 4];
            acc[0][0] += a.x * b.x; acc[0][1] += a.x * b.y; acc[0][2] += a.x * b.z; acc[0][3] += a.x * b.w;
            acc[1][0] += a.y * b.x; acc[1][1] += a.y * b.y; acc[1][2] += a.y * b.z; acc[1][3] += a.y * b.w;
            acc[2][0] += a.z * b.x; acc[2][1] += a.z * b.y; acc[2][2] += a.z * b.z; acc[2][3] += a.z * b.w;
            acc[3][0] += a.w * b.x; acc[3][1] += a.w * b.y; acc[3][2] += a.w * b.z; acc[3][3] += a.w * b.w;
        }
    }

    #pragma unroll
    for (int i = 0; i < 4; i++) {
        int r = bm + tr * 4 + i;
        if (r >= M) continue;
        float s = (MODE == 2) ? 1.f : d_dinv[r];
        #pragma unroll
        for (int j = 0; j < 4; j++) {
            float v = acc[i][j];
            if (MODE == 0) v += d_bc[tc * 4 + j];
            acc[i][j] = v * s;
        }
        size_t o = (size_t)r * 64 + tc * 4;
        if (MODE == 0 || MODE == 1) {
            // fp16 messages for the scatter gathers
            __half2 h01 = __floats2half2_rn(acc[i][0], acc[i][1]);
            __half2 h23 = __floats2half2_rn(acc[i][2], acc[i][3]);
            uint2 pk = make_uint2(*(unsigned*)&h01, *(unsigned*)&h23);
            *(uint2*)(d_Gh + o) = pk;
            // f32 accumulator seed (self-loop term)
            float* accdst = (MODE == 0) ? d_ACC : d_ACC2;
            *(float4*)(accdst + o) = *(float4*)acc[i];
        }
        if (MODE == 2) {                                 // TD in fp16
            __half2 h01 = __floats2half2_rn(acc[i][0], acc[i][1]);
            __half2 h23 = __floats2half2_rn(acc[i][2], acc[i][3]);
            uint2 pk = make_uint2(*(unsigned*)&h01, *(unsigned*)&h23);
            *(uint2*)(d_TDh + o) = pk;
        }
    }
}

// ---------------- edge scatter-add: acc[col] += g[row] --------------------
// 16 threads/edge: gather 4 halves (8B), convert, ONE red.v4.f32 (16B).
// Raw edge buffer read inline (is32 branch is uniform).
template <int WHICH>   // 1 -> d_ACC, 2 -> d_ACC2
__global__ void __launch_bounds__(256) k_scatter(const int* __restrict__ buf, int E) {
    const int is32 = d_is32;
    int total = E * 16;
    for (int t = blockIdx.x * blockDim.x + threadIdx.x; t < total;
         t += gridDim.x * blockDim.x) {
        int e = t >> 4, c = t & 15;
        int r  = __ldg(&buf[is32 ? e : 2 * e]);
        int cl = __ldg(&buf[is32 ? (E + e) : 2 * (E + e)]);
        uint2 pk = __ldg((const uint2*)(d_Gh + (size_t)r * 64 + c * 4));
        float2 f01 = __half22float2(*(__half2*)&pk.x);
        float2 f23 = __half22float2(*(__half2*)&pk.y);
        float4 v = make_float4(f01.x, f01.y, f23.x, f23.y);
        float* p = (WHICH == 1 ? d_ACC : d_ACC2) + (size_t)cl * 64 + c * 4;
        red_add_v4(p, v);
    }
}

// ---------------- bilinear decoder: out[e] = H2[src]·TD[dst] + bb ---------
// fp16 tables, 8 threads/edge, 16B loads; raw edge buffer read inline.
__global__ void __launch_bounds__(256) k_bilinear(const int* __restrict__ buf, int E,
                                                  const float* __restrict__ bb,
                                                  float* __restrict__ out) {
    const int is32 = d_is32;
    const float bias = bb[0];
    const uint4* Hp = (const uint4*)d_Hh;    // 8 halves per uint4
    const uint4* Tp = (const uint4*)d_TDh;
    int total = E * 8;
    for (int t = blockIdx.x * blockDim.x + threadIdx.x; t < total;
         t += gridDim.x * blockDim.x) {
        int e = t >> 3, c = t & 7;
        int s = __ldg(&buf[is32 ? e : 2 * e]);
        int d = __ldg(&buf[is32 ? (E + e) : 2 * (E + e)]);
        uint4 a = __ldg(Hp + (size_t)s * 8 + c);
        uint4 b = __ldg(Tp + (size_t)d * 8 + c);
        float p = 0.f;
        {
            float2 fa, fb;
            fa = __half22float2(*(__half2*)&a.x); fb = __half22float2(*(__half2*)&b.x);
            p += fa.x * fb.x + fa.y * fb.y;
            fa = __half22float2(*(__half2*)&a.y); fb = __half22float2(*(__half2*)&b.y);
            p += fa.x * fb.x + fa.y * fb.y;
            fa = __half22float2(*(__half2*)&a.z); fb = __half22float2(*(__half2*)&b.z);
            p += fa.x * fb.x + fa.y * fb.y;
            fa = __half22float2(*(__half2*)&a.w); fb = __half22float2(*(__half2*)&b.w);
            p += fa.x * fb.x + fa.y * fb.y;
        }
        p += __shfl_xor_sync(0xffffffffu, p, 4);
        p += __shfl_xor_sync(0xffffffffu, p, 2);
        p += __shfl_xor_sync(0xffffffffu, p, 1);
        if (c == 0) out[e] = p + bias;
    }
}

// ---------------- launcher: kernel launches ONLY ---------------------------
extern "C" void kernel_launch(void* const* d_in, const int* in_sizes, int n_in,
                              void* d_out, int out_size) {
    const float* x     = (const float*)d_in[0];
    const int*   eip   = (const int*)d_in[1];    // prediction edges (raw words)
    const int*   eipos = (const int*)d_in[2];    // message edges (raw words)
    const float* W0    = (const float*)d_in[3];
    const float* b0    = (const float*)d_in[4];
    const float* W1    = (const float*)d_in[5];
    const float* b1    = (const float*)d_in[6];
    const float* W2    = (const float*)d_in[7];
    const float* b2    = (const float*)d_in[8];
    const float* Wb    = (const float*)d_in[9];
    const float* bb    = (const float*)d_in[10];
    float* out = (float*)d_out;

    const int N     = in_sizes[0] / FDIM;
    const int Epred = in_sizes[1] / 2;
    const int Epos  = in_sizes[2] / 2;
    const int GS    = 8192;

    // init (zero deg + dtype detect), degree from raw buffer, dinv
    k_init<<<(N + 255) / 256, 256>>>((const unsigned int*)eip, 2 * Epred, N);
    k_deg<<<(Epos + 255) / 256, 256>>>(eipos, Epos);
    k_dinv<<<(N + 255) / 256, 256>>>(N);

    // weight prep: Wc = W0@W1, bc = b0@W1, WbT
    k_prep<<<32, 256>>>(W0, b0, W1, Wb);

    // g1 = (x@Wc + bc)*dinv -> d_Gh (fp16), seeds acc1 f32
    gemmF<FDIM, 0><<<(N + 63) / 64, 256>>>(x, nullptr, nullptr, N);

    // conv1 aggregate: acc1[col] += g1[row]  (fp16 gather, f32 red)
    k_scatter<1><<<GS, 256>>>(eipos, Epos);

    // g2 = (relu(dinv*acc1 + b1) @ W2)*dinv -> d_Gh, seeds acc2
    gemmF<HDIM, 1><<<(N + 63) / 64, 256>>>(nullptr, W2, b1, N);

    // conv2 aggregate: acc2[col] += g2[row]
    k_scatter<2><<<GS, 256>>>(eipos, Epos);

    // H2 = dinv*acc2 + b2 (fp16 to d_Hh in loader); TD = H2@WbT -> d_TDh fp16
    gemmF<HDIM, 2><<<(N + 63) / 64, 256>>>(nullptr, nullptr, b2, N);

    // logits[e] = H2[src] · TD[dst] + bb   (fp16 tables, raw edge buffer)
    k_bilinear<<<GS, 256>>>(eip, Epred, bb, out);
}